// round 8
// baseline (speedup 1.0000x reference)
#include <cuda_runtime.h>

// Problem constants (fixed by the reference): B=8, C=64, H=W=256.
#define Bn   8
#define Cn   64
#define Hn   256
#define Wn   256
#define HWn  (Hn * Wn)          // 65536
#define NPIX (Bn * HWn)         // 524288
#define NBUCKET 16              // source-row bands of 16 rows
#define TPB  256
#define K2BX 148                // blocks per bucket (1 wave per bucket-ish)

// Static device scratch (allowed; no runtime allocation).
__device__ int g_cnt[NBUCKET];
__device__ int g_list[NBUCKET][NPIX];   // 16 * 524288 * 4B = 32 MiB

// ---------------------------------------------------------------- K0: reset
__global__ void k0_reset()
{
    if (threadIdx.x < NBUCKET) g_cnt[threadIdx.x] = 0;
}

// Shared sampling math (must be IDENTICAL in K1 and K2 for determinism).
__device__ __forceinline__ void sample_setup(
    int h, int w, float px, float py, float mv,
    float& w00, float& w01, float& w10, float& w11,
    int& o00, int& o01, int& o10, int& o11, int& y0c_out)
{
    // vgrid = 2*(coord+phi)/(dim-1) - 1 + 2*phi ; unnormalize (align_corners=False)
    const float vx = 2.0f * ((float)w + px) / (float)(Wn - 1) - 1.0f + 2.0f * px;
    const float vy = 2.0f * ((float)h + py) / (float)(Hn - 1) - 1.0f + 2.0f * py;
    const float ix = (vx + 1.0f) * (0.5f * (float)Wn) - 0.5f;
    const float iy = (vy + 1.0f) * (0.5f * (float)Hn) - 0.5f;

    const float x0f = floorf(ix);
    const float y0f = floorf(iy);
    const int   x0  = (int)x0f;
    const int   y0  = (int)y0f;
    const int   x1  = x0 + 1;
    const int   y1  = y0 + 1;

    const float wx1 = ix - x0f;
    const float wx0 = 1.0f - wx1;
    const float wy1 = iy - y0f;
    const float wy0 = 1.0f - wy1;

    const float vx0 = (x0 >= 0 && x0 < Wn) ? 1.0f : 0.0f;
    const float vx1 = (x1 >= 0 && x1 < Wn) ? 1.0f : 0.0f;
    const float vy0 = (y0 >= 0 && y0 < Hn) ? 1.0f : 0.0f;
    const float vy1 = (y1 >= 0 && y1 < Hn) ? 1.0f : 0.0f;

    // Fold validity AND mask into corner weights (zeros padding, out *= m)
    w00 = wy0 * wx0 * vy0 * vx0 * mv;
    w01 = wy0 * wx1 * vy0 * vx1 * mv;
    w10 = wy1 * wx0 * vy1 * vx0 * mv;
    w11 = wy1 * wx1 * vy1 * vx1 * mv;

    const int x0c = min(max(x0, 0), Wn - 1);
    const int x1c = min(max(x1, 0), Wn - 1);
    const int y0c = min(max(y0, 0), Hn - 1);
    const int y1c = min(max(y1, 0), Hn - 1);

    o00 = y0c * Wn + x0c;
    o01 = y0c * Wn + x1c;
    o10 = y1c * Wn + x0c;
    o11 = y1c * Wn + x1c;
    y0c_out = y0c;
}

// --------------------------------------- K1: streaming zero-fill + classify
__global__ __launch_bounds__(TPB)
void k1_zero_classify(const float* __restrict__ phi,
                      const float* __restrict__ m,
                      float* __restrict__ out)
{
    const int t = blockIdx.x * TPB + threadIdx.x;   // 0..524287 (one pixel)

    // Dense zero-fill: 16 rounds of fully-coalesced float4 streaming stores.
    // 16 * 524288 float4 = 33,554,432 floats = the whole output.
    const float4 z = make_float4(0.0f, 0.0f, 0.0f, 0.0f);
    float4* __restrict__ o4 = (float4*)out;
#pragma unroll
    for (int i = 0; i < 16; ++i)
        __stcs(o4 + (size_t)i * NPIX + t, z);

    // Classify this pixel.
    const int b  = t >> 16;
    const int hw = t & (HWn - 1);
    const int h  = hw >> 8;
    const int w  = hw & (Wn - 1);

    const float px = phi[(b * 2 + 0) * HWn + hw];
    const float py = phi[(b * 2 + 1) * HWn + hw];
    const float mv = m[b * HWn + hw];

    float w00, w01, w10, w11;
    int o00, o01, o10, o11, y0c;
    sample_setup(h, w, px, py, mv, w00, w01, w10, w11, o00, o01, o10, o11, y0c);

    const bool pvalid = (w00 != 0.0f) | (w01 != 0.0f) |
                        (w10 != 0.0f) | (w11 != 0.0f);
    if (pvalid) {
        const int band = y0c >> 4;            // 16 source-row bands
        const int pos  = atomicAdd(&g_cnt[band], 1);
        g_list[band][pos] = t;
    }
}

// ------------------- K2: bucket-major gather (source-row-band confinement)
__global__ __launch_bounds__(TPB)
void k2_gather(const float* __restrict__ phi,
               const float* __restrict__ x_enc,
               const float* __restrict__ m,
               float* __restrict__ out)
{
    const int bucket = blockIdx.y;
    const int ntask  = g_cnt[bucket] << 6;    // valid pixels * 64 channels

    for (int t = blockIdx.x * TPB + threadIdx.x; t < ntask;
         t += K2BX * TPB) {
        const int pid = g_list[bucket][t >> 6];
        const int ch  = t & 63;

        const int b  = pid >> 16;
        const int hw = pid & (HWn - 1);
        const int h  = hw >> 8;
        const int w  = hw & (Wn - 1);

        // Recompute weights (tiny, L2-hot phi/m reads; identical math).
        const float px = phi[(b * 2 + 0) * HWn + hw];
        const float py = phi[(b * 2 + 1) * HWn + hw];
        const float mv = m[b * HWn + hw];

        float w00, w01, w10, w11;
        int o00, o01, o10, o11, y0c;
        sample_setup(h, w, px, py, mv, w00, w01, w10, w11,
                     o00, o01, o10, o11, y0c);

        const float* __restrict__ pc = x_enc + (b * Cn + ch) * HWn;
        float a = 0.0f, bv = 0.0f, cv = 0.0f, dv = 0.0f;
        if (w00 != 0.0f) a  = __ldg(pc + o00);
        if (w01 != 0.0f) bv = __ldg(pc + o01);
        if (w10 != 0.0f) cv = __ldg(pc + o10);
        if (w11 != 0.0f) dv = __ldg(pc + o11);
        const float v = fmaf(w00, a, fmaf(w01, bv, fmaf(w10, cv, w11 * dv)));

        // Default (write-back) store: scattered dirty sectors park in L2,
        // flushed off the critical path.
        out[(b * Cn + ch) * HWn + hw] = v;
    }
}

extern "C" void kernel_launch(void* const* d_in, const int* in_sizes, int n_in,
                              void* d_out, int out_size)
{
    const float* phi   = (const float*)d_in[0];
    const float* x_enc = (const float*)d_in[1];
    const float* m     = (const float*)d_in[2];
    float* out         = (float*)d_out;

    k0_reset<<<1, 32>>>();
    k1_zero_classify<<<NPIX / TPB, TPB>>>(phi, m, out);   // 2048 blocks
    dim3 g2(K2BX, NBUCKET);                                // bucket-major order
    k2_gather<<<g2, TPB>>>(phi, x_enc, m, out);
}

// round 9
// speedup vs baseline: 1.0692x; 1.0692x over previous
#include <cuda_runtime.h>

// Problem constants (fixed by the reference): B=8, C=64, H=W=256.
#define Bn   8
#define Cn   64
#define Hn   256
#define Wn   256
#define HWn  (Hn * Wn)          // 65536
#define NPIX (Bn * HWn)         // 524288
#define FULLM 0xFFFFFFFFu
#define TPB  256

// Static device scratch (compile-time; no runtime allocation).
__device__ int    g_cnt;
__device__ int    g_pid[NPIX];     // valid pixel ids (compacted)
__device__ float4 g_wgt[NPIX];     // per valid pixel: 4 corner weights
__device__ int4   g_off[NPIX];     // per valid pixel: 4 corner offsets

// ---------------------------------------------------------------- K0: reset
__global__ void k0_reset() { if (threadIdx.x == 0) g_cnt = 0; }

// --------------------------- K1: streaming zero-fill + classify + compact
__global__ __launch_bounds__(TPB)
void k1_zero_classify(const float* __restrict__ phi,
                      const float* __restrict__ m,
                      float* __restrict__ out)
{
    const int t    = blockIdx.x * TPB + threadIdx.x;  // one pixel per thread
    const int lane = threadIdx.x & 31;

    // Dense zero-fill: 16 rounds of coalesced float4 streaming stores
    // (16 * 524288 float4 = entire 33.5M-element output).
    const float4 z = make_float4(0.0f, 0.0f, 0.0f, 0.0f);
    float4* __restrict__ o4 = (float4*)out;
#pragma unroll
    for (int i = 0; i < 16; ++i)
        __stcs(o4 + (size_t)i * NPIX + t, z);

    // ---- classify this pixel (identical math to the passing kernels) ----
    const int b  = t >> 16;
    const int hw = t & (HWn - 1);
    const int h  = hw >> 8;
    const int w  = hw & (Wn - 1);

    const float px = phi[(b * 2 + 0) * HWn + hw];
    const float py = phi[(b * 2 + 1) * HWn + hw];
    const float mv = m[b * HWn + hw];

    // vgrid = 2*(coord+phi)/(dim-1) - 1 + 2*phi ; unnormalize (align_corners=False)
    const float vx = 2.0f * ((float)w + px) / (float)(Wn - 1) - 1.0f + 2.0f * px;
    const float vy = 2.0f * ((float)h + py) / (float)(Hn - 1) - 1.0f + 2.0f * py;
    const float ix = (vx + 1.0f) * (0.5f * (float)Wn) - 0.5f;
    const float iy = (vy + 1.0f) * (0.5f * (float)Hn) - 0.5f;

    const float x0f = floorf(ix);
    const float y0f = floorf(iy);
    const int   x0  = (int)x0f;
    const int   y0  = (int)y0f;
    const int   x1  = x0 + 1;
    const int   y1  = y0 + 1;

    const float wx1 = ix - x0f;
    const float wx0 = 1.0f - wx1;
    const float wy1 = iy - y0f;
    const float wy0 = 1.0f - wy1;

    const float vx0 = (x0 >= 0 && x0 < Wn) ? 1.0f : 0.0f;
    const float vx1 = (x1 >= 0 && x1 < Wn) ? 1.0f : 0.0f;
    const float vy0 = (y0 >= 0 && y0 < Hn) ? 1.0f : 0.0f;
    const float vy1 = (y1 >= 0 && y1 < Hn) ? 1.0f : 0.0f;

    const float w00 = wy0 * wx0 * vy0 * vx0 * mv;
    const float w01 = wy0 * wx1 * vy0 * vx1 * mv;
    const float w10 = wy1 * wx0 * vy1 * vx0 * mv;
    const float w11 = wy1 * wx1 * vy1 * vx1 * mv;

    const bool pvalid = (w00 != 0.0f) | (w01 != 0.0f) |
                        (w10 != 0.0f) | (w11 != 0.0f);

    // Warp-aggregated append: ONE atomic per warp (single global counter).
    const unsigned blt = __ballot_sync(FULLM, pvalid);
    if (blt) {
        int base = 0;
        const int leader = __ffs(blt) - 1;
        if (lane == leader) base = atomicAdd(&g_cnt, __popc(blt));
        base = __shfl_sync(FULLM, base, leader);
        if (pvalid) {
            const int pos = base + __popc(blt & ((1u << lane) - 1u));
            const int x0c = min(max(x0, 0), Wn - 1);
            const int x1c = min(max(x1, 0), Wn - 1);
            const int y0c = min(max(y0, 0), Hn - 1);
            const int y1c = min(max(y1, 0), Hn - 1);
            g_pid[pos] = t;
            g_wgt[pos] = make_float4(w00, w01, w10, w11);
            g_off[pos] = make_int4(y0c * Wn + x0c, y0c * Wn + x1c,
                                   y1c * Wn + x0c, y1c * Wn + x1c);
        }
    }
}

// --------------------------------- K2: pure gather over the compacted list
#define K2BLOCKS 2048
__global__ __launch_bounds__(TPB)
void k2_gather(const float* __restrict__ x_enc,
               float* __restrict__ out)
{
    const int nval  = g_cnt;
    const int ntask = nval << 6;                  // valid pixels * 64 channels

    for (int t = blockIdx.x * TPB + threadIdx.x; t < ntask;
         t += K2BLOCKS * TPB) {
        const int j  = t >> 6;                    // list index (warp-uniform-ish)
        const int ch = t & 63;

        const int    pid = g_pid[j];
        const float4 wv  = g_wgt[j];
        const int4   ov  = g_off[j];

        const int b  = pid >> 16;
        const int hw = pid & (HWn - 1);

        const float* __restrict__ pc = x_enc + (b * Cn + ch) * HWn;
        float a = 0.0f, bv = 0.0f, cv = 0.0f, dv = 0.0f;
        if (wv.x != 0.0f) a  = __ldg(pc + ov.x);
        if (wv.y != 0.0f) bv = __ldg(pc + ov.y);
        if (wv.z != 0.0f) cv = __ldg(pc + ov.z);
        if (wv.w != 0.0f) dv = __ldg(pc + ov.w);
        const float v = fmaf(wv.x, a, fmaf(wv.y, bv, fmaf(wv.z, cv, wv.w * dv)));

        // Scattered 4B stores (~4.8MB total) — default write-back, parked in L2.
        out[(b * Cn + ch) * HWn + hw] = v;
    }
}

extern "C" void kernel_launch(void* const* d_in, const int* in_sizes, int n_in,
                              void* d_out, int out_size)
{
    const float* phi   = (const float*)d_in[0];
    const float* x_enc = (const float*)d_in[1];
    const float* m     = (const float*)d_in[2];
    float* out         = (float*)d_out;

    k0_reset<<<1, 32>>>();
    k1_zero_classify<<<NPIX / TPB, TPB>>>(phi, m, out);   // 2048 blocks
    k2_gather<<<K2BLOCKS, TPB>>>(x_enc, out);
}